// round 5
// baseline (speedup 1.0000x reference)
#include <cuda_runtime.h>
#include <cuda_bf16.h>
#include <math.h>
#include <stdint.h>

// Problem constants
#define BB 512
#define TT 1024
#define FF 128
#define UU 50
#define GG 200            // 4*U gate columns
#define NROWS (BB * TT)   // 524288 GEMM rows
#define MT16 (NROWS / 16) // 32768 m16 tiles
#define NCTA_P 296        // proj CTAs (2 per SM, pairs split N)
#define WSTRIDE (148 * 8) // warp stride per N-half

// Scratch: xproj[b*T + t][200] = x[b,t,:] @ kernel (fp32)
__device__ float g_xproj[(size_t)NROWS * GG];

// ---------------------------------------------------------------------------
// helpers
// ---------------------------------------------------------------------------
__device__ __forceinline__ uint32_t smem_u32(const void* p) {
    uint32_t a;
    asm("{ .reg .u64 t; cvta.to.shared.u64 t, %1; cvt.u32.u64 %0, t; }" : "=r"(a) : "l"(p));
    return a;
}

__device__ __forceinline__ uint32_t bf2pack(float a, float b) {
    __nv_bfloat162 t = __floats2bfloat162_rn(a, b);
    return *reinterpret_cast<uint32_t*>(&t);
}

// pack top 16 bits of two floats into bf16x2 (truncation split, 1 instr)
__device__ __forceinline__ uint32_t hipack(float a, float b) {
    uint32_t d;
    asm("prmt.b32 %0, %1, %2, 0x7632;" : "=r"(d)
        : "r"(__float_as_uint(a)), "r"(__float_as_uint(b)));
    return d;
}
__device__ __forceinline__ float trunc_hi(float v) {
    return __uint_as_float(__float_as_uint(v) & 0xffff0000u);
}

__device__ __forceinline__ void mma16816(float* d, uint32_t a0, uint32_t a1,
                                         uint32_t a2, uint32_t a3,
                                         uint32_t b0, uint32_t b1) {
    asm volatile(
        "mma.sync.aligned.m16n8k16.row.col.f32.bf16.bf16.f32 "
        "{%0,%1,%2,%3}, {%4,%5,%6,%7}, {%8,%9}, {%0,%1,%2,%3};"
        : "+f"(d[0]), "+f"(d[1]), "+f"(d[2]), "+f"(d[3])
        : "r"(a0), "r"(a1), "r"(a2), "r"(a3), "r"(b0), "r"(b1));
}

__device__ __forceinline__ void ldsm_x4(uint32_t& r0, uint32_t& r1,
                                        uint32_t& r2, uint32_t& r3, uint32_t addr) {
    asm volatile("ldmatrix.sync.aligned.m8n8.x4.shared.b16 {%0,%1,%2,%3}, [%4];"
                 : "=r"(r0), "=r"(r1), "=r"(r2), "=r"(r3) : "r"(addr));
}

// ---------------------------------------------------------------------------
// Kernel 1: projection GEMM xproj = x @ W via HMMA bf16, 3-term hi/lo split.
//   296 CTAs x 256 threads; CTA pairs split N: half0 n-tiles [0,13), half1
//   n-tiles [12,25) (tile 12 computed by both, identical stores - benign).
//   56.6KB smem -> 2 CTAs/SM. One ldmatrix.x4 per n-tile fetches B hi+lo.
//   A fragments built in registers from GMEM (truncation hi/lo split).
// ---------------------------------------------------------------------------
#define NT 13                        // n-tiles per CTA half
#define NBROWS (NT * 8)              // 104 B rows staged
#define KP 136                       // padded B row stride in bf16
#define BROW (KP * 2)                // 272 bytes
#define SMB_LO (NBROWS * BROW)       // 28288
#define SMB_TOTAL (2 * NBROWS * BROW)// 56576 bytes

__global__ __launch_bounds__(256, 2)
void proj_kernel(const float* __restrict__ x, const float* __restrict__ W) {
    extern __shared__ char smem[];
    const uint32_t sb = smem_u32(smem);
    const int tid = threadIdx.x;
    const int wid = tid >> 5;
    const int lane = tid & 31;
    const int half = blockIdx.x & 1;
    const int noff = half ? 96 : 0;   // global n offset of this CTA's slice

    // Stage B = W^T hi/lo (rounding split) for n in [noff, noff+104).
    for (int idx = tid; idx < NBROWS * FF; idx += 256) {
        int nl = idx >> 7;
        int k = idx & 127;
        float v = W[k * GG + (noff + nl)];
        __nv_bfloat16 hi = __float2bfloat16_rn(v);
        float lo = v - __bfloat162float(hi);
        uint32_t off = (uint32_t)(nl * BROW + k * 2);
        *reinterpret_cast<__nv_bfloat16*>(smem + off) = hi;
        *reinterpret_cast<__nv_bfloat16*>(smem + SMB_LO + off) = __float2bfloat16_rn(lo);
    }
    __syncthreads();

    // ldmatrix.x4 lane addressing: groups of 8 lanes -> (hi k0, hi k8, lo k0, lo k8)
    const int l8 = lane & 7;
    const int grp = lane >> 3;
    const uint32_t lmOff = (uint32_t)(l8 * BROW + (grp & 1) * 16 + (grp >> 1) * SMB_LO);

    const int r = lane >> 2;     // 0..7  (fragment row)
    const int cq = lane & 3;     // 0..3  (fragment col quad)

    for (int mt = (blockIdx.x >> 1) * 8 + wid; mt < MT16; mt += WSTRIDE) {
        const size_t row0 = (size_t)mt * 16 + r;

        const float* __restrict__ p0 = x + row0 * FF;        // row r
        const float* __restrict__ p1 = x + (row0 + 8) * FF;  // row r+8

        float acc[NT][4];
#pragma unroll
        for (int j = 0; j < NT; ++j) {
            acc[j][0] = 0.f; acc[j][1] = 0.f; acc[j][2] = 0.f; acc[j][3] = 0.f;
        }

#pragma unroll
        for (int kk = 0; kk < 8; ++kk) {
            const int k0 = kk * 16;
            // A fragment floats: (r,k0+2c),(r+8,k0+2c),(r,k0+2c+8),(r+8,k0+2c+8)
            float2 f0 = *(const float2*)(p0 + k0 + 2 * cq);
            float2 f1 = *(const float2*)(p1 + k0 + 2 * cq);
            float2 f2 = *(const float2*)(p0 + k0 + 2 * cq + 8);
            float2 f3 = *(const float2*)(p1 + k0 + 2 * cq + 8);

            uint32_t ah0 = hipack(f0.x, f0.y);
            uint32_t ah1 = hipack(f1.x, f1.y);
            uint32_t ah2 = hipack(f2.x, f2.y);
            uint32_t ah3 = hipack(f3.x, f3.y);
            uint32_t al0 = bf2pack(f0.x - trunc_hi(f0.x), f0.y - trunc_hi(f0.y));
            uint32_t al1 = bf2pack(f1.x - trunc_hi(f1.x), f1.y - trunc_hi(f1.y));
            uint32_t al2 = bf2pack(f2.x - trunc_hi(f2.x), f2.y - trunc_hi(f2.y));
            uint32_t al3 = bf2pack(f3.x - trunc_hi(f3.x), f3.y - trunc_hi(f3.y));

            const uint32_t kOff = sb + (uint32_t)(k0 * 2) + lmOff;
#pragma unroll
            for (int j = 0; j < NT; ++j) {
                uint32_t bh0, bh1, bl0, bl1;
                ldsm_x4(bh0, bh1, bl0, bl1, kOff + (uint32_t)(j * 8 * BROW));
                mma16816(acc[j], ah0, ah1, ah2, ah3, bh0, bh1);
                mma16816(acc[j], ah0, ah1, ah2, ah3, bl0, bl1);
                mma16816(acc[j], al0, al1, al2, al3, bh0, bh1);
            }
        }

        // store D: thread holds (row r, cols 2cq..) and (row r+8, same)
        float* __restrict__ d0 = g_xproj + row0 * GG + noff + 2 * cq;
        float* __restrict__ d1 = g_xproj + (row0 + 8) * GG + noff + 2 * cq;
#pragma unroll
        for (int j = 0; j < NT; ++j) {
            *(float2*)(d0 + j * 8) = make_float2(acc[j][0], acc[j][1]);
            *(float2*)(d1 + j * 8) = make_float2(acc[j][2], acc[j][3]);
        }
    }
}

// ---------------------------------------------------------------------------
// Kernel 2: persistent LSTM recurrence + dense head.
//   1 batch row per CTA (512 CTAs x 224 threads) - restores occupancy.
//   HW tanh.approx gates; xproj prefetched TWO steps ahead (~800cyc slack
//   > 577cyc DRAM latency).
// ---------------------------------------------------------------------------
__device__ __forceinline__ float fast_tanh(float v) {
    float y;
    asm("tanh.approx.f32 %0, %1;" : "=f"(y) : "f"(v));
    return y;
}
__device__ __forceinline__ float fast_sig(float v) {
    return fmaf(fast_tanh(0.5f * v), 0.5f, 0.5f);
}

__global__ __launch_bounds__(224)
void lstm_kernel(const float* __restrict__ R, const float* __restrict__ bias,
                 const float* __restrict__ dw, const float* __restrict__ db,
                 float* __restrict__ out) {
    __shared__ __align__(16) float h_s[52];
    __shared__ float z_s[200];

    const int tid = threadIdx.x;
    const int b = blockIdx.x;

    float rw[UU];
    float bv = 0.f;
    if (tid < GG) {
#pragma unroll
        for (int u = 0; u < UU; ++u) rw[u] = R[u * GG + tid];
        bv = bias[tid];
    }
    if (tid < 52) h_s[tid] = 0.f;
    float c = 0.f;
    __syncthreads();

    const float* __restrict__ xp = g_xproj + (size_t)b * TT * GG;

    float xv = 0.f, xA = 0.f;                 // t, t+1 in flight
    if (tid < GG) { xv = xp[tid]; xA = xp[GG + tid]; }

#pragma unroll 1
    for (int t = 0; t < TT; ++t) {
        float xB = 0.f;
        if (tid < GG) {
            int tn = (t + 2 < TT) ? (t + 2) : (TT - 1);
            xB = xp[(size_t)tn * GG + tid];   // prefetch t+2

            // z = h_{t-1} . rec_col  (4 independent accumulator chains)
            float acc4[4] = {0.f, 0.f, 0.f, 0.f};
#pragma unroll
            for (int u4 = 0; u4 < 12; ++u4) {
                float4 h4 = *(const float4*)(h_s + 4 * u4);
                float a = acc4[u4 & 3];
                a = fmaf(rw[4 * u4 + 0], h4.x, a);
                a = fmaf(rw[4 * u4 + 1], h4.y, a);
                a = fmaf(rw[4 * u4 + 2], h4.z, a);
                a = fmaf(rw[4 * u4 + 3], h4.w, a);
                acc4[u4 & 3] = a;
            }
            acc4[0] = fmaf(rw[48], h_s[48], acc4[0]);
            acc4[1] = fmaf(rw[49], h_s[49], acc4[1]);
            float acc = (acc4[0] + acc4[1]) + (acc4[2] + acc4[3]) + (bv + xv);

            z_s[tid] = (tid >= 100 && tid < 150) ? fast_tanh(acc) : fast_sig(acc);
        }
        __syncthreads();
        if (tid < UU) {
            float gi = z_s[tid];
            float gf = z_s[tid + 50];
            float gg = z_s[tid + 100];
            float go = z_s[tid + 150];
            c = fmaf(gf, c, gi * gg);
            h_s[tid] = go * fast_tanh(c);
        }
        __syncthreads();
        xv = xA; xA = xB;
    }

    // dense head: out[b] = h . dense_w + dense_b
    if (tid == 0) {
        float s = db[0];
#pragma unroll
        for (int u = 0; u < UU; ++u) s += h_s[u] * dw[u];
        out[b] = s;
    }
}

// ---------------------------------------------------------------------------
extern "C" void kernel_launch(void* const* d_in, const int* in_sizes, int n_in,
                              void* d_out, int out_size) {
    const float* x    = (const float*)d_in[0];  // [512,1024,128]
    const float* W    = (const float*)d_in[1];  // [128,200]
    const float* R    = (const float*)d_in[2];  // [50,200]
    const float* bias = (const float*)d_in[3];  // [200]
    const float* dw   = (const float*)d_in[4];  // [50]
    const float* db   = (const float*)d_in[5];  // [1]
    float* out = (float*)d_out;                 // [512]
    (void)in_sizes; (void)n_in; (void)out_size;

    cudaFuncSetAttribute(proj_kernel,
                         cudaFuncAttributeMaxDynamicSharedMemorySize, SMB_TOTAL);

    proj_kernel<<<NCTA_P, 256, SMB_TOTAL>>>(x, W);
    lstm_kernel<<<BB, 224>>>(R, bias, dw, db, out);
}

// round 6
// speedup vs baseline: 1.3706x; 1.3706x over previous
#include <cuda_runtime.h>
#include <cuda_bf16.h>
#include <math.h>
#include <stdint.h>

// Problem constants
#define BB 512
#define TT 1024
#define FF 128
#define UU 50
#define GG 200            // 4*U gate columns
#define NROWS (BB * TT)   // 524288 GEMM rows
#define MT16 (NROWS / 16) // 32768 m16 tiles
#define NCTA_P 296        // proj CTAs (2 per SM, pairs split N)
#define WSTRIDE (148 * 8) // warp stride per N-half

// Scratch: xproj[b*T + t][200] = x[b,t,:] @ kernel (fp32)
__device__ float g_xproj[(size_t)NROWS * GG];

// ---------------------------------------------------------------------------
// helpers
// ---------------------------------------------------------------------------
__device__ __forceinline__ uint32_t smem_u32(const void* p) {
    uint32_t a;
    asm("{ .reg .u64 t; cvta.to.shared.u64 t, %1; cvt.u32.u64 %0, t; }" : "=r"(a) : "l"(p));
    return a;
}

__device__ __forceinline__ uint32_t bf2pack(float a, float b) {
    __nv_bfloat162 t = __floats2bfloat162_rn(a, b);
    return *reinterpret_cast<uint32_t*>(&t);
}

// pack top 16 bits of two floats into bf16x2 (truncation split, 1 instr)
__device__ __forceinline__ uint32_t hipack(float a, float b) {
    uint32_t d;
    asm("prmt.b32 %0, %1, %2, 0x7632;" : "=r"(d)
        : "r"(__float_as_uint(a)), "r"(__float_as_uint(b)));
    return d;
}
__device__ __forceinline__ float trunc_hi(float v) {
    return __uint_as_float(__float_as_uint(v) & 0xffff0000u);
}

__device__ __forceinline__ void mma16816(float* d, uint32_t a0, uint32_t a1,
                                         uint32_t a2, uint32_t a3,
                                         uint32_t b0, uint32_t b1) {
    asm volatile(
        "mma.sync.aligned.m16n8k16.row.col.f32.bf16.bf16.f32 "
        "{%0,%1,%2,%3}, {%4,%5,%6,%7}, {%8,%9}, {%0,%1,%2,%3};"
        : "+f"(d[0]), "+f"(d[1]), "+f"(d[2]), "+f"(d[3])
        : "r"(a0), "r"(a1), "r"(a2), "r"(a3), "r"(b0), "r"(b1));
}

__device__ __forceinline__ void ldsm_x4(uint32_t& r0, uint32_t& r1,
                                        uint32_t& r2, uint32_t& r3, uint32_t addr) {
    asm volatile("ldmatrix.sync.aligned.m8n8.x4.shared.b16 {%0,%1,%2,%3}, [%4];"
                 : "=r"(r0), "=r"(r1), "=r"(r2), "=r"(r3) : "r"(addr));
}

// ---------------------------------------------------------------------------
// Kernel 0: noop (launch-order padding so ncu -s 5 -c 1 lands on proj_kernel)
// ---------------------------------------------------------------------------
__global__ void noop_kernel() {}

// ---------------------------------------------------------------------------
// Kernel 1: projection GEMM xproj = x @ W via HMMA bf16, 3-term hi/lo split.
//   296 CTAs x 256 threads; CTA pairs split N: half0 n-tiles [0,13), half1
//   n-tiles [12,25) (tile 12 computed by both, identical stores - benign).
//   56.6KB smem, ~90 regs -> 2 CTAs/SM. One ldmatrix.x4 per n-tile fetches
//   B hi+lo. A fragments built in registers from GMEM (truncation hi/lo).
// ---------------------------------------------------------------------------
#define NT 13                        // n-tiles per CTA half
#define NBROWS (NT * 8)              // 104 B rows staged
#define KP 136                       // padded B row stride in bf16
#define BROW (KP * 2)                // 272 bytes
#define SMB_LO (NBROWS * BROW)       // 28288
#define SMB_TOTAL (2 * NBROWS * BROW)// 56576 bytes

__global__ __launch_bounds__(256, 2)
void proj_kernel(const float* __restrict__ x, const float* __restrict__ W) {
    extern __shared__ char smem[];
    const uint32_t sb = smem_u32(smem);
    const int tid = threadIdx.x;
    const int wid = tid >> 5;
    const int lane = tid & 31;
    const int half = blockIdx.x & 1;
    const int noff = half ? 96 : 0;   // global n offset of this CTA's slice

    // Stage B = W^T hi/lo (rounding split) for n in [noff, noff+104).
    for (int idx = tid; idx < NBROWS * FF; idx += 256) {
        int nl = idx >> 7;
        int k = idx & 127;
        float v = W[k * GG + (noff + nl)];
        __nv_bfloat16 hi = __float2bfloat16_rn(v);
        float lo = v - __bfloat162float(hi);
        uint32_t off = (uint32_t)(nl * BROW + k * 2);
        *reinterpret_cast<__nv_bfloat16*>(smem + off) = hi;
        *reinterpret_cast<__nv_bfloat16*>(smem + SMB_LO + off) = __float2bfloat16_rn(lo);
    }
    __syncthreads();

    // ldmatrix.x4 lane addressing: 8-lane groups -> (hi k0, hi k8, lo k0, lo k8)
    const int l8 = lane & 7;
    const int grp = lane >> 3;
    const uint32_t lmOff = (uint32_t)(l8 * BROW + (grp & 1) * 16 + (grp >> 1) * SMB_LO);

    const int r = lane >> 2;     // 0..7  (fragment row)
    const int cq = lane & 3;     // 0..3  (fragment col quad)

    for (int mt = (blockIdx.x >> 1) * 8 + wid; mt < MT16; mt += WSTRIDE) {
        const size_t row0 = (size_t)mt * 16 + r;

        const float* __restrict__ p0 = x + row0 * FF;        // row r
        const float* __restrict__ p1 = x + (row0 + 8) * FF;  // row r+8

        float acc[NT][4];
#pragma unroll
        for (int j = 0; j < NT; ++j) {
            acc[j][0] = 0.f; acc[j][1] = 0.f; acc[j][2] = 0.f; acc[j][3] = 0.f;
        }

#pragma unroll
        for (int kk = 0; kk < 8; ++kk) {
            const int k0 = kk * 16;
            // A fragment floats: (r,k0+2c),(r+8,k0+2c),(r,k0+2c+8),(r+8,k0+2c+8)
            float2 f0 = *(const float2*)(p0 + k0 + 2 * cq);
            float2 f1 = *(const float2*)(p1 + k0 + 2 * cq);
            float2 f2 = *(const float2*)(p0 + k0 + 2 * cq + 8);
            float2 f3 = *(const float2*)(p1 + k0 + 2 * cq + 8);

            uint32_t ah0 = hipack(f0.x, f0.y);
            uint32_t ah1 = hipack(f1.x, f1.y);
            uint32_t ah2 = hipack(f2.x, f2.y);
            uint32_t ah3 = hipack(f3.x, f3.y);
            uint32_t al0 = bf2pack(f0.x - trunc_hi(f0.x), f0.y - trunc_hi(f0.y));
            uint32_t al1 = bf2pack(f1.x - trunc_hi(f1.x), f1.y - trunc_hi(f1.y));
            uint32_t al2 = bf2pack(f2.x - trunc_hi(f2.x), f2.y - trunc_hi(f2.y));
            uint32_t al3 = bf2pack(f3.x - trunc_hi(f3.x), f3.y - trunc_hi(f3.y));

            const uint32_t kOff = sb + (uint32_t)(k0 * 2) + lmOff;
#pragma unroll
            for (int j = 0; j < NT; ++j) {
                uint32_t bh0, bh1, bl0, bl1;
                ldsm_x4(bh0, bh1, bl0, bl1, kOff + (uint32_t)(j * 8 * BROW));
                mma16816(acc[j], ah0, ah1, ah2, ah3, bh0, bh1);
                mma16816(acc[j], ah0, ah1, ah2, ah3, bl0, bl1);
                mma16816(acc[j], al0, al1, al2, al3, bh0, bh1);
            }
        }

        // store D: thread holds (row r, cols 2cq..) and (row r+8, same)
        float* __restrict__ d0 = g_xproj + row0 * GG + noff + 2 * cq;
        float* __restrict__ d1 = g_xproj + (row0 + 8) * GG + noff + 2 * cq;
#pragma unroll
        for (int j = 0; j < NT; ++j) {
            *(float2*)(d0 + j * 8) = make_float2(acc[j][0], acc[j][1]);
            *(float2*)(d1 + j * 8) = make_float2(acc[j][2], acc[j][3]);
        }
    }
}

// ---------------------------------------------------------------------------
// Kernel 2: persistent LSTM recurrence + dense head.
//   R2 structure: 1 batch row/CTA, 512 CTAs x 224 threads, 1-step prefetch,
//   __launch_bounds__(224,4) forces <=72 regs -> 4 CTAs/SM, single wave.
//   HW tanh.approx gates; streaming (__ldcs) xproj reads.
// ---------------------------------------------------------------------------
__device__ __forceinline__ float fast_tanh(float v) {
    float y;
    asm("tanh.approx.f32 %0, %1;" : "=f"(y) : "f"(v));
    return y;
}
__device__ __forceinline__ float fast_sig(float v) {
    return fmaf(fast_tanh(0.5f * v), 0.5f, 0.5f);
}

__global__ __launch_bounds__(224, 4)
void lstm_kernel(const float* __restrict__ R, const float* __restrict__ bias,
                 const float* __restrict__ dw, const float* __restrict__ db,
                 float* __restrict__ out) {
    __shared__ __align__(16) float h_s[52];
    __shared__ float z_s[200];

    const int tid = threadIdx.x;
    const int b = blockIdx.x;

    float rw[UU];
    float bv = 0.f;
    if (tid < GG) {
#pragma unroll
        for (int u = 0; u < UU; ++u) rw[u] = R[u * GG + tid];
        bv = bias[tid];
    }
    if (tid < 52) h_s[tid] = 0.f;
    float c = 0.f;
    __syncthreads();

    const float* __restrict__ xp = g_xproj + (size_t)b * TT * GG;
    float xv = (tid < GG) ? __ldcs(xp + tid) : 0.f;

#pragma unroll 1
    for (int t = 0; t < TT; ++t) {
        float xn = 0.f;
        if (tid < GG) {
            int tn = (t + 1 < TT) ? (t + 1) : (TT - 1);
            xn = __ldcs(xp + (size_t)tn * GG + tid);   // prefetch next step

            // z = h_{t-1} . rec_col  (4 independent accumulator chains)
            float acc4[4] = {0.f, 0.f, 0.f, 0.f};
#pragma unroll
            for (int u4 = 0; u4 < 12; ++u4) {
                float4 h4 = *(const float4*)(h_s + 4 * u4);
                float a = acc4[u4 & 3];
                a = fmaf(rw[4 * u4 + 0], h4.x, a);
                a = fmaf(rw[4 * u4 + 1], h4.y, a);
                a = fmaf(rw[4 * u4 + 2], h4.z, a);
                a = fmaf(rw[4 * u4 + 3], h4.w, a);
                acc4[u4 & 3] = a;
            }
            acc4[0] = fmaf(rw[48], h_s[48], acc4[0]);
            acc4[1] = fmaf(rw[49], h_s[49], acc4[1]);
            float acc = (acc4[0] + acc4[1]) + (acc4[2] + acc4[3]) + (bv + xv);

            z_s[tid] = (tid >= 100 && tid < 150) ? fast_tanh(acc) : fast_sig(acc);
        }
        __syncthreads();
        if (tid < UU) {
            float gi = z_s[tid];
            float gf = z_s[tid + 50];
            float gg = z_s[tid + 100];
            float go = z_s[tid + 150];
            c = fmaf(gf, c, gi * gg);
            h_s[tid] = go * fast_tanh(c);
        }
        __syncthreads();
        xv = xn;
    }

    // dense head: out[b] = h . dense_w + dense_b
    if (tid == 0) {
        float s = db[0];
#pragma unroll
        for (int u = 0; u < UU; ++u) s += h_s[u] * dw[u];
        out[b] = s;
    }
}

// ---------------------------------------------------------------------------
extern "C" void kernel_launch(void* const* d_in, const int* in_sizes, int n_in,
                              void* d_out, int out_size) {
    const float* x    = (const float*)d_in[0];  // [512,1024,128]
    const float* W    = (const float*)d_in[1];  // [128,200]
    const float* R    = (const float*)d_in[2];  // [50,200]
    const float* bias = (const float*)d_in[3];  // [200]
    const float* dw   = (const float*)d_in[4];  // [50]
    const float* db   = (const float*)d_in[5];  // [1]
    float* out = (float*)d_out;                 // [512]
    (void)in_sizes; (void)n_in; (void)out_size;

    cudaFuncSetAttribute(proj_kernel,
                         cudaFuncAttributeMaxDynamicSharedMemorySize, SMB_TOTAL);

    // Launch period = 4 so ncu (-s 5 -c 1) profiles launch #6 = proj_kernel.
    noop_kernel<<<1, 32>>>();
    proj_kernel<<<NCTA_P, 256, SMB_TOTAL>>>(x, W);
    lstm_kernel<<<BB, 224>>>(R, bias, dw, db, out);
    noop_kernel<<<1, 32>>>();
}

// round 8
// speedup vs baseline: 1.4531x; 1.0602x over previous
#include <cuda_runtime.h>
#include <cuda_bf16.h>
#include <math.h>
#include <stdint.h>

// Problem constants
#define BB 512
#define TT 1024
#define FF 128
#define UU 50
#define GG 200            // 4*U gate columns
#define NROWS (BB * TT)   // 524288 GEMM rows
#define MT16 (NROWS / 16) // 32768 m16 tiles
#define NCTA_P 444        // proj CTAs (3 per SM, triples split N)
#define WSTRIDE (148 * 8) // m-tile warp stride per N-group

// Scratch: xproj[b*T + t][200] = x[b,t,:] @ kernel (fp32)
__device__ float g_xproj[(size_t)NROWS * GG];

// ---------------------------------------------------------------------------
// helpers
// ---------------------------------------------------------------------------
__device__ __forceinline__ uint32_t smem_u32(const void* p) {
    uint32_t a;
    asm("{ .reg .u64 t; cvta.to.shared.u64 t, %1; cvt.u32.u64 %0, t; }" : "=r"(a) : "l"(p));
    return a;
}

__device__ __forceinline__ uint32_t bf2pack(float a, float b) {
    __nv_bfloat162 t = __floats2bfloat162_rn(a, b);
    return *reinterpret_cast<uint32_t*>(&t);
}

// pack top 16 bits of two floats into bf16x2 (truncation split, 1 instr)
__device__ __forceinline__ uint32_t hipack(float a, float b) {
    uint32_t d;
    asm("prmt.b32 %0, %1, %2, 0x7632;" : "=r"(d)
        : "r"(__float_as_uint(a)), "r"(__float_as_uint(b)));
    return d;
}
__device__ __forceinline__ float trunc_hi(float v) {
    return __uint_as_float(__float_as_uint(v) & 0xffff0000u);
}

__device__ __forceinline__ void mma16816(float* d, uint32_t a0, uint32_t a1,
                                         uint32_t a2, uint32_t a3,
                                         uint32_t b0, uint32_t b1) {
    asm volatile(
        "mma.sync.aligned.m16n8k16.row.col.f32.bf16.bf16.f32 "
        "{%0,%1,%2,%3}, {%4,%5,%6,%7}, {%8,%9}, {%0,%1,%2,%3};"
        : "+f"(d[0]), "+f"(d[1]), "+f"(d[2]), "+f"(d[3])
        : "r"(a0), "r"(a1), "r"(a2), "r"(a3), "r"(b0), "r"(b1));
}

__device__ __forceinline__ void ldsm_x4(uint32_t& r0, uint32_t& r1,
                                        uint32_t& r2, uint32_t& r3, uint32_t addr) {
    asm volatile("ldmatrix.sync.aligned.m8n8.x4.shared.b16 {%0,%1,%2,%3}, [%4];"
                 : "=r"(r0), "=r"(r1), "=r"(r2), "=r"(r3) : "r"(addr));
}

// packed fp32x2 FMA (Blackwell family): d = a*b + d, element-wise on 2 floats
__device__ __forceinline__ void fma2(uint64_t& d, uint64_t a, uint64_t b) {
    asm("fma.rn.f32x2 %0, %1, %2, %0;" : "+l"(d) : "l"(a), "l"(b));
}
__device__ __forceinline__ uint64_t pk2(float lo, float hi) {
    uint64_t r;
    asm("mov.b64 %0, {%1, %2};" : "=l"(r) : "f"(lo), "f"(hi));
    return r;
}
__device__ __forceinline__ float up2sum(uint64_t v) {
    float lo, hi;
    asm("mov.b64 {%0, %1}, %2;" : "=f"(lo), "=f"(hi) : "l"(v));
    return lo + hi;
}

// ---------------------------------------------------------------------------
// Kernel 0: noop (launch-order padding for ncu sampling: period 3)
// ---------------------------------------------------------------------------
__global__ void noop_kernel() {}

// ---------------------------------------------------------------------------
// Kernel 1: projection GEMM xproj = x @ W via HMMA bf16, 3-term hi/lo split.
//   444 CTAs x 256 threads; CTA triples split N: group g covers n-tiles
//   [8g, 8g+9) (tiles 8,16 duplicated across groups - identical stores).
//   39.2KB smem -> 3 CTAs/SM (6 warps/SMSP latency hiding).
//   One ldmatrix.x4 per n-tile fetches B hi+lo; A built in registers.
// ---------------------------------------------------------------------------
#define NT 9                         // n-tiles per CTA group
#define NBROWS (NT * 8)              // 72 B rows staged
#define KP 136                       // padded B row stride in bf16
#define BROW (KP * 2)                // 272 bytes
#define SMB_LO (NBROWS * BROW)       // 19584
#define SMB_TOTAL (2 * NBROWS * BROW)// 39168 bytes

__global__ __launch_bounds__(256, 3)
void proj_kernel(const float* __restrict__ x, const float* __restrict__ W) {
    extern __shared__ char smem[];
    const uint32_t sb = smem_u32(smem);
    const int tid = threadIdx.x;
    const int wid = tid >> 5;
    const int lane = tid & 31;
    const int grpN = blockIdx.x % 3;
    const int noff = grpN * 64;       // global n float-offset of this slice

    // Stage B = W^T hi/lo (rounding split) for n in [noff, noff+72).
    for (int idx = tid; idx < NBROWS * FF; idx += 256) {
        int nl = idx >> 7;
        int k = idx & 127;
        float v = W[k * GG + (noff + nl)];
        __nv_bfloat16 hi = __float2bfloat16_rn(v);
        float lo = v - __bfloat162float(hi);
        uint32_t off = (uint32_t)(nl * BROW + k * 2);
        *reinterpret_cast<__nv_bfloat16*>(smem + off) = hi;
        *reinterpret_cast<__nv_bfloat16*>(smem + SMB_LO + off) = __float2bfloat16_rn(lo);
    }
    __syncthreads();

    // ldmatrix.x4 lane addressing: 8-lane groups -> (hi k0, hi k8, lo k0, lo k8)
    const int l8 = lane & 7;
    const int grp = lane >> 3;
    const uint32_t lmOff = (uint32_t)(l8 * BROW + (grp & 1) * 16 + (grp >> 1) * SMB_LO);

    const int r = lane >> 2;     // 0..7  (fragment row)
    const int cq = lane & 3;     // 0..3  (fragment col quad)

    for (int mt = (blockIdx.x / 3) * 8 + wid; mt < MT16; mt += WSTRIDE) {
        const size_t row0 = (size_t)mt * 16 + r;

        const float* __restrict__ p0 = x + row0 * FF;        // row r
        const float* __restrict__ p1 = x + (row0 + 8) * FF;  // row r+8

        float acc[NT][4];
#pragma unroll
        for (int j = 0; j < NT; ++j) {
            acc[j][0] = 0.f; acc[j][1] = 0.f; acc[j][2] = 0.f; acc[j][3] = 0.f;
        }

#pragma unroll
        for (int kk = 0; kk < 8; ++kk) {
            const int k0 = kk * 16;
            // A fragment floats: (r,k0+2c),(r+8,k0+2c),(r,k0+2c+8),(r+8,k0+2c+8)
            float2 f0 = *(const float2*)(p0 + k0 + 2 * cq);
            float2 f1 = *(const float2*)(p1 + k0 + 2 * cq);
            float2 f2 = *(const float2*)(p0 + k0 + 2 * cq + 8);
            float2 f3 = *(const float2*)(p1 + k0 + 2 * cq + 8);

            uint32_t ah0 = hipack(f0.x, f0.y);
            uint32_t ah1 = hipack(f1.x, f1.y);
            uint32_t ah2 = hipack(f2.x, f2.y);
            uint32_t ah3 = hipack(f3.x, f3.y);
            uint32_t al0 = bf2pack(f0.x - trunc_hi(f0.x), f0.y - trunc_hi(f0.y));
            uint32_t al1 = bf2pack(f1.x - trunc_hi(f1.x), f1.y - trunc_hi(f1.y));
            uint32_t al2 = bf2pack(f2.x - trunc_hi(f2.x), f2.y - trunc_hi(f2.y));
            uint32_t al3 = bf2pack(f3.x - trunc_hi(f3.x), f3.y - trunc_hi(f3.y));

            const uint32_t kOff = sb + (uint32_t)(k0 * 2) + lmOff;
#pragma unroll
            for (int j = 0; j < NT; ++j) {
                uint32_t bh0, bh1, bl0, bl1;
                ldsm_x4(bh0, bh1, bl0, bl1, kOff + (uint32_t)(j * 8 * BROW));
                mma16816(acc[j], ah0, ah1, ah2, ah3, bh0, bh1);
                mma16816(acc[j], ah0, ah1, ah2, ah3, bl0, bl1);
                mma16816(acc[j], al0, al1, al2, al3, bh0, bh1);
            }
        }

        // store D: thread holds (row r, cols 2cq..) and (row r+8, same)
        float* __restrict__ d0 = g_xproj + row0 * GG + noff + 2 * cq;
        float* __restrict__ d1 = g_xproj + (row0 + 8) * GG + noff + 2 * cq;
#pragma unroll
        for (int j = 0; j < NT; ++j) {
            *(float2*)(d0 + j * 8) = make_float2(acc[j][0], acc[j][1]);
            *(float2*)(d1 + j * 8) = make_float2(acc[j][2], acc[j][3]);
        }
    }
}

// ---------------------------------------------------------------------------
// Kernel 2: persistent LSTM recurrence + dense head.
//   1 row/CTA, 512 CTAs x 224 threads, 4 CTAs/SM. Recurrent dot uses packed
//   fma.rn.f32x2 (halves FMA issue). HW tanh.approx gates. 1-step prefetch.
// ---------------------------------------------------------------------------
__device__ __forceinline__ float fast_tanh(float v) {
    float y;
    asm("tanh.approx.f32 %0, %1;" : "=f"(y) : "f"(v));
    return y;
}
__device__ __forceinline__ float fast_sig(float v) {
    return fmaf(fast_tanh(0.5f * v), 0.5f, 0.5f);
}

__global__ __launch_bounds__(224, 4)
void lstm_kernel(const float* __restrict__ R, const float* __restrict__ bias,
                 const float* __restrict__ dw, const float* __restrict__ db,
                 float* __restrict__ out) {
    __shared__ __align__(16) float h_s[52];
    __shared__ float z_s[200];

    const int tid = threadIdx.x;
    const int b = blockIdx.x;

    uint64_t rw2[25];      // packed rec_kernel column pairs (u, u+1)
    float bv = 0.f;
    if (tid < GG) {
#pragma unroll
        for (int u2 = 0; u2 < 25; ++u2)
            rw2[u2] = pk2(R[(2 * u2) * GG + tid], R[(2 * u2 + 1) * GG + tid]);
        bv = bias[tid];
    }
    if (tid < 52) h_s[tid] = 0.f;
    float c = 0.f;
    __syncthreads();

    const float* __restrict__ xp = g_xproj + (size_t)b * TT * GG;
    float xv = (tid < GG) ? __ldcs(xp + tid) : 0.f;

#pragma unroll 1
    for (int t = 0; t < TT; ++t) {
        float xn = 0.f;
        if (tid < GG) {
            int tn = (t + 1 < TT) ? (t + 1) : (TT - 1);
            xn = __ldcs(xp + (size_t)tn * GG + tid);   // prefetch next step

            // z = h_{t-1} . rec_col via packed f32x2 (4 independent chains)
            uint64_t z2 = pk2(0.f, 0.f);
            uint64_t acc2[4] = {z2, z2, z2, z2};
#pragma unroll
            for (int i = 0; i < 12; ++i) {
                ulonglong2 h2 = *(const ulonglong2*)(h_s + 4 * i);  // pairs 2i, 2i+1
                fma2(acc2[(2 * i) & 3], rw2[2 * i], h2.x);
                fma2(acc2[(2 * i + 1) & 3], rw2[2 * i + 1], h2.y);
            }
            fma2(acc2[0], rw2[24], *(const uint64_t*)(h_s + 48));   // pair 24
            float acc = (up2sum(acc2[0]) + up2sum(acc2[1])) +
                        (up2sum(acc2[2]) + up2sum(acc2[3])) + (bv + xv);

            z_s[tid] = (tid >= 100 && tid < 150) ? fast_tanh(acc) : fast_sig(acc);
        }
        __syncthreads();
        if (tid < UU) {
            float gi = z_s[tid];
            float gf = z_s[tid + 50];
            float gg = z_s[tid + 100];
            float go = z_s[tid + 150];
            c = fmaf(gf, c, gi * gg);
            h_s[tid] = go * fast_tanh(c);
        }
        __syncthreads();
        xv = xn;
    }

    // dense head: out[b] = h . dense_w + dense_b
    if (tid == 0) {
        float s = db[0];
#pragma unroll
        for (int u = 0; u < UU; ++u) s += h_s[u] * dw[u];
        out[b] = s;
    }
}

// ---------------------------------------------------------------------------
extern "C" void kernel_launch(void* const* d_in, const int* in_sizes, int n_in,
                              void* d_out, int out_size) {
    const float* x    = (const float*)d_in[0];  // [512,1024,128]
    const float* W    = (const float*)d_in[1];  // [128,200]
    const float* R    = (const float*)d_in[2];  // [50,200]
    const float* bias = (const float*)d_in[3];  // [200]
    const float* dw   = (const float*)d_in[4];  // [50]
    const float* db   = (const float*)d_in[5];  // [1]
    float* out = (float*)d_out;                 // [512]
    (void)in_sizes; (void)n_in; (void)out_size;

    cudaFuncSetAttribute(proj_kernel,
                         cudaFuncAttributeMaxDynamicSharedMemorySize, SMB_TOTAL);

    // Launch period = 3: sampled index {3,15}->proj, 7->lstm, 11->noop.
    proj_kernel<<<NCTA_P, 256, SMB_TOTAL>>>(x, W);
    lstm_kernel<<<BB, 224>>>(R, bias, dw, db, out);
    noop_kernel<<<1, 32>>>();
}